// round 3
// baseline (speedup 1.0000x reference)
#include <cuda_runtime.h>
#include <cstdint>

// IF neuron over x[T=4, B=32, H=512, W=1024] fp32:
//   per spatial position p: v=0; for t: v+=x[t][p]; s=(v>=1)?1:0; out[t][p]=s; v-=s
// Pure streaming: 268 MB in + 268 MB out.
// R3: 8 float4 loads per thread (MLP=8), streaming cache hints (ldcs/stcs).

static constexpr long long SPATIAL  = 32LL * 512LL * 1024LL;  // 16,777,216
static constexpr long long SPATIAL4 = SPATIAL / 4;            // 4,194,304 float4s
static constexpr int THREADS = 256;
static constexpr int F4_PER_BLOCK = 2 * THREADS;              // 512 float4s / t-plane / block
static constexpr long long NBLK = SPATIAL4 / F4_PER_BLOCK;    // 8192 (exact)

__device__ __forceinline__ float step1(float& v, float xt) {
    v += xt;
    float s = (v >= 1.0f) ? 1.0f : 0.0f;
    v -= s;
    return s;
}

__device__ __forceinline__ float4 ldcs4(const float4* p) {
    return __ldcs(p);
}
__device__ __forceinline__ void stcs4(float4* p, float4 v) {
    __stcs(p, v);
}

// Scan one lane-component across the 4 t-planes.
__device__ __forceinline__ void scan4(const float x0, const float x1,
                                      const float x2, const float x3,
                                      float& o0, float& o1, float& o2, float& o3) {
    float v = 0.0f;
    o0 = step1(v, x0);
    o1 = step1(v, x1);
    o2 = step1(v, x2);
    o3 = step1(v, x3);
}

__global__ __launch_bounds__(THREADS)
void if_neuron_kernel(const float4* __restrict__ x, float4* __restrict__ out) {
    long long base = (long long)blockIdx.x * F4_PER_BLOCK + threadIdx.x;
    long long iA = base;             // first float4 of this thread
    long long iB = base + THREADS;   // second float4 (warp-contiguous per instruction)

    // 8 independent 128-bit streaming loads, front-batched (MLP=8)
    float4 a0 = ldcs4(x + iA + 0 * SPATIAL4);
    float4 a1 = ldcs4(x + iA + 1 * SPATIAL4);
    float4 a2 = ldcs4(x + iA + 2 * SPATIAL4);
    float4 a3 = ldcs4(x + iA + 3 * SPATIAL4);
    float4 b0 = ldcs4(x + iB + 0 * SPATIAL4);
    float4 b1 = ldcs4(x + iB + 1 * SPATIAL4);
    float4 b2 = ldcs4(x + iB + 2 * SPATIAL4);
    float4 b3 = ldcs4(x + iB + 3 * SPATIAL4);

    float4 p0, p1, p2, p3;   // outputs for iA
    float4 q0, q1, q2, q3;   // outputs for iB

    scan4(a0.x, a1.x, a2.x, a3.x, p0.x, p1.x, p2.x, p3.x);
    scan4(a0.y, a1.y, a2.y, a3.y, p0.y, p1.y, p2.y, p3.y);
    scan4(a0.z, a1.z, a2.z, a3.z, p0.z, p1.z, p2.z, p3.z);
    scan4(a0.w, a1.w, a2.w, a3.w, p0.w, p1.w, p2.w, p3.w);

    scan4(b0.x, b1.x, b2.x, b3.x, q0.x, q1.x, q2.x, q3.x);
    scan4(b0.y, b1.y, b2.y, b3.y, q0.y, q1.y, q2.y, q3.y);
    scan4(b0.z, b1.z, b2.z, b3.z, q0.z, q1.z, q2.z, q3.z);
    scan4(b0.w, b1.w, b2.w, b3.w, q0.w, q1.w, q2.w, q3.w);

    stcs4(out + iA + 0 * SPATIAL4, p0);
    stcs4(out + iB + 0 * SPATIAL4, q0);
    stcs4(out + iA + 1 * SPATIAL4, p1);
    stcs4(out + iB + 1 * SPATIAL4, q1);
    stcs4(out + iA + 2 * SPATIAL4, p2);
    stcs4(out + iB + 2 * SPATIAL4, q2);
    stcs4(out + iA + 3 * SPATIAL4, p3);
    stcs4(out + iB + 3 * SPATIAL4, q3);
}

extern "C" void kernel_launch(void* const* d_in, const int* in_sizes, int n_in,
                              void* d_out, int out_size) {
    const float4* x = (const float4*)d_in[0];
    float4* out = (float4*)d_out;
    if_neuron_kernel<<<(unsigned)NBLK, THREADS>>>(x, out);
}